// round 13
// baseline (speedup 1.0000x reference)
#include <cuda_runtime.h>
#include <cuda_bf16.h>
#include <cstdint>
#include <math.h>

// Problem constants (fixed: B=4, T=2048, H=2048)
#define BB 4
#define TT 2048
#define HH 2048
#define MM (BB*TT)              // 8192 rows

// Scan decomposition (single-pass, decoupled lookback)
#define SC_CHUNK 64
#define SC_NCH (TT/SC_CHUNK)    // 32 chunks
#define SC_N (BB*SC_NCH*HH)     // lookback slots

// ---------------------------------------------------------------------------
// Scratch (device globals — no runtime allocation allowed)
// ---------------------------------------------------------------------------
__device__ float g_gate[(size_t)MM*HH];   // raw i projection (GEMM out)
__device__ float g_v[(size_t)MM*HH];      // raw f projection (GEMM out)
__device__ float g_gp[(size_t)MM*HH];     // raw g projection
__device__ float g_o[(size_t)MM*HH];      // scan output
__device__ float g_aggA[SC_N];            // lookback: chunk aggregate A
__device__ float g_aggB[SC_N];            // lookback: chunk aggregate B
__device__ float g_inc[SC_N];             // lookback: inclusive prefix h
__device__ int   g_flag[SC_N];            // lookback: 0 none / 1 agg / 2 inclusive
// int8 2-limb quantized operands
__device__ int8_t g_X0[(size_t)MM*HH];    // X limb0 (reused for normed o)
__device__ int8_t g_X1[(size_t)MM*HH];    // X limb1
__device__ int8_t g_W0[4][(size_t)HH*HH];
__device__ int8_t g_W1[4][(size_t)HH*HH];
__device__ float  g_sx[MM];               // per-row scale of X / normed o
__device__ float  g_sw[4][HH];            // per-row scale of each W

// Fast approx reciprocal (single MUFU.RCP, ~2^-22 rel err)
__device__ __forceinline__ float rcpa(float x) {
    float y; asm("rcp.approx.f32 %0, %1;" : "=f"(y) : "f"(x)); return y;
}
// Fast sigmoid: 1 EX2 + 1 RCP
__device__ __forceinline__ float sigf(float x) {
    return rcpa(1.0f + __expf(fminf(-x, 30.0f)));
}

// ---------------------------------------------------------------------------
// PTX helpers (sm_80-era -> valid on compute_100)
// ---------------------------------------------------------------------------
__device__ __forceinline__ uint32_t smem_u32(const void* p) {
    uint32_t a; asm("{ .reg .u64 t; cvta.to.shared.u64 t, %1; cvt.u32.u64 %0, t; }" : "=r"(a) : "l"(p));
    return a;
}
__device__ __forceinline__ void cp16(uint32_t saddr, const void* g) {
    asm volatile("cp.async.cg.shared.global [%0], [%1], 16;" :: "r"(saddr), "l"(g));
}
#define CP_COMMIT() asm volatile("cp.async.commit_group;" ::: "memory")
#define CP_WAIT1()  asm volatile("cp.async.wait_group 1;" ::: "memory")

__device__ __forceinline__ void ldm_x4(uint32_t a, uint32_t* r) {
    asm volatile("ldmatrix.sync.aligned.m8n8.x4.shared.b16 {%0,%1,%2,%3}, [%4];"
        : "=r"(r[0]), "=r"(r[1]), "=r"(r[2]), "=r"(r[3]) : "r"(a));
}
// s8 MMA: m16n8k32, s32 accumulate
__device__ __forceinline__ void mma_s8(int* c, const uint32_t* a, const uint32_t* b) {
    asm volatile("mma.sync.aligned.m16n8k32.row.col.s32.s8.s8.s32 "
        "{%0,%1,%2,%3}, {%4,%5,%6,%7}, {%8,%9}, {%0,%1,%2,%3};"
        : "+r"(c[0]), "+r"(c[1]), "+r"(c[2]), "+r"(c[3])
        : "r"(a[0]), "r"(a[1]), "r"(a[2]), "r"(a[3]), "r"(b[0]), "r"(b[1]));
}

__device__ __forceinline__ uint32_t pack4(int b0, int b1, int b2, int b3) {
    return (uint32_t)(b0 & 255) | ((uint32_t)(b1 & 255) << 8)
         | ((uint32_t)(b2 & 255) << 16) | ((uint32_t)(b3 & 255) << 24);
}

// ---------------------------------------------------------------------------
// Lookback flag reset (graph replay leaves flags at 2)
// ---------------------------------------------------------------------------
__global__ __launch_bounds__(256) void reset_flags()
{
    const int i = blockIdx.x * 256 + threadIdx.x;
    ((int4*)g_flag)[i] = make_int4(0, 0, 0, 0);
}

// ---------------------------------------------------------------------------
// Row quantizer: x ~= s*(a0 + a1/128), a0,a1 int8, s = rowmax/127.
// ---------------------------------------------------------------------------
__device__ __forceinline__ void quant_row_body(
    const float* __restrict__ x, int8_t* __restrict__ d0,
    int8_t* __restrict__ d1, float* __restrict__ sarr, int row)
{
    const int t = threadIdx.x;
    float4 v0 = ((const float4*)x)[t*2];
    float4 v1 = ((const float4*)x)[t*2 + 1];
    float xs[8] = {v0.x, v0.y, v0.z, v0.w, v1.x, v1.y, v1.z, v1.w};
    float m = 0.f;
#pragma unroll
    for (int j = 0; j < 8; j++) m = fmaxf(m, fabsf(xs[j]));
    __shared__ float red[8];
#pragma unroll
    for (int o = 16; o; o >>= 1) m = fmaxf(m, __shfl_xor_sync(0xffffffffu, m, o));
    if ((t & 31) == 0) red[t >> 5] = m;
    __syncthreads();
    if (t < 8) {
        float mm = red[t];
#pragma unroll
        for (int o = 4; o; o >>= 1) mm = fmaxf(mm, __shfl_xor_sync(0xffu, mm, o));
        if (t == 0) red[0] = mm;
    }
    __syncthreads();
    m = red[0];
    const float s = (m > 0.f) ? m / 127.f : 1.f;
    const float inv = 127.f * rcpa(fmaxf(m, 1e-30f));
    int a0[8], a1[8];
#pragma unroll
    for (int j = 0; j < 8; j++) {
        float q = xs[j] * inv;
        float r0 = rintf(q);
        a0[j] = (int)r0;
        a1[j] = (int)rintf((q - r0) * 128.f);
    }
    ((uint2*)(d0 + (size_t)row * HH))[t] = make_uint2(pack4(a0[0],a0[1],a0[2],a0[3]), pack4(a0[4],a0[5],a0[6],a0[7]));
    ((uint2*)(d1 + (size_t)row * HH))[t] = make_uint2(pack4(a1[0],a1[1],a1[2],a1[3]), pack4(a1[4],a1[5],a1[6],a1[7]));
    if (t == 0) sarr[row] = s;
}

__global__ __launch_bounds__(256) void quant_x_kernel(const float* __restrict__ src)
{
    const int row = blockIdx.x;
    quant_row_body(src + (size_t)row * HH, g_X0, g_X1, g_sx, row);
}

// All 4 weights in one launch: blockIdx.y selects the weight.
__global__ __launch_bounds__(256) void quant_w_kernel(
    const float* __restrict__ s0, const float* __restrict__ s1,
    const float* __restrict__ s2, const float* __restrict__ s3)
{
    const int row = blockIdx.x;
    const int w = blockIdx.y;
    const float* src = (w == 0) ? s0 : (w == 1) ? s1 : (w == 2) ? s2 : s3;
    quant_row_body(src + (size_t)row * HH, g_W0[w], g_W1[w], g_sw[w], row);
}

// ===========================================================================
// 2-limb int8 GEMM on mma.sync m16n8k32
// CTA 128x64, warp tile 32x32, KC=64, **3-stage** cp.async, 2 CTAs/SM.
// (R11 structure + R6 pipeline depth: WAIT1 keeps stage c+1 streaming
//  during compute of stage c — removes the per-chunk WAIT0 drain bubble.)
// ===========================================================================
#define KC 64
#define ROWB 80
#define A_MATB (128*ROWB)
#define B_MATB (64*ROWB)
#define STGB (2*A_MATB + 2*B_MATB)   // 30720 B per stage
#define OFF_A1 A_MATB
#define OFF_B0 (2*A_MATB)
#define OFF_B1 (2*A_MATB + B_MATB)
#define NKC (HH/KC)
#define NSTG 3                        // 92160 B/CTA, 2 CTAs/SM = 184 KB

__global__ __launch_bounds__(256, 2) void gemm_mma(
    const int8_t* __restrict__ x0, const int8_t* __restrict__ x1,
    const float* __restrict__ sA, int wbase,
    float* __restrict__ C0, float* __restrict__ C1, float* __restrict__ C2)
{
    extern __shared__ __align__(16) char smem[];
    const uint32_t sb = smem_u32(smem);
    const int tid = threadIdx.x, lane = tid & 31, wid = tid >> 5;
    const int wm = wid >> 1, wn = wid & 1;
    const int bm = blockIdx.y * 128, bn = blockIdx.x * 64;
    const int w = wbase + blockIdx.z;
    const int8_t* w0 = g_W0[w];
    const int8_t* w1 = g_W1[w];
    const float* sB = g_sw[w];
    float* C = (blockIdx.z == 0) ? C0 : (blockIdx.z == 1) ? C1 : C2;

    int P[2][4][4] = {}, Q[2][4][4] = {};

    auto load_stage = [&](int buf, int k0) {
        const uint32_t sbase = sb + buf * STGB;
#pragma unroll
        for (int i = 0; i < 6; i++) {
            int idx = i * 256 + tid;
            const int8_t* base; uint32_t moff; int row0, r, vv;
            if (i < 4) {
                int limb = idx >> 9;
                int rem = idx & 511;
                r = rem >> 2; vv = rem & 3;
                base = limb ? x1 : x0;
                moff = limb ? (uint32_t)OFF_A1 : 0u;
                row0 = bm;
            } else {
                int rem = idx - 1024;
                int limb = rem >> 8;
                rem &= 255;
                r = rem >> 2; vv = rem & 3;
                base = limb ? w1 : w0;
                moff = limb ? (uint32_t)OFF_B1 : (uint32_t)OFF_B0;
                row0 = bn;
            }
            cp16(sbase + moff + (uint32_t)(r * ROWB + vv * 16),
                 base + (size_t)(row0 + r) * HH + k0 + vv * 16);
        }
    };

    const uint32_t aRowOff = (uint32_t)((wm * 32 + (lane & 15)) * ROWB + (lane >> 4) * 16);
    const uint32_t bRowOff = (uint32_t)((wn * 32 + ((lane >> 4) << 3) + (lane & 7)) * ROWB
                                        + ((lane >> 3) & 1) * 16);

    load_stage(0, 0);      CP_COMMIT();
    load_stage(1, KC);     CP_COMMIT();

    for (int c = 0; c < NKC; c++) {
        CP_WAIT1();                         // stage c landed (c+1 may be in flight)
        __syncthreads();                    // all warps done with buffer (c+2)%3
        if (c + 2 < NKC) { load_stage((c + 2) % NSTG, (c + 2) * KC); CP_COMMIT(); }
        else CP_COMMIT();                   // keep group accounting uniform

        const uint32_t s0 = sb + (c % NSTG) * STGB;
#pragma unroll
        for (int ks = 0; ks < 2; ks++) {
            const uint32_t kOff = ks * 32;
            uint32_t a0f[2][4], a1f[2][4];
#pragma unroll
            for (int mt = 0; mt < 2; mt++) {
                ldm_x4(s0 + 0      + mt * 16 * ROWB + kOff + aRowOff, a0f[mt]);
                ldm_x4(s0 + OFF_A1 + mt * 16 * ROWB + kOff + aRowOff, a1f[mt]);
            }
#pragma unroll
            for (int p = 0; p < 2; p++) {
                uint32_t b0f[4], b1f[4];
                ldm_x4(s0 + OFF_B0 + p * 16 * ROWB + kOff + bRowOff, b0f);
                ldm_x4(s0 + OFF_B1 + p * 16 * ROWB + kOff + bRowOff, b1f);
                mma_s8(P[0][2*p],   a0f[0], &b0f[0]);
                mma_s8(P[1][2*p],   a0f[1], &b0f[0]);
                mma_s8(P[0][2*p+1], a0f[0], &b0f[2]);
                mma_s8(P[1][2*p+1], a0f[1], &b0f[2]);
                mma_s8(Q[0][2*p],   a0f[0], &b1f[0]);
                mma_s8(Q[1][2*p],   a0f[1], &b1f[0]);
                mma_s8(Q[0][2*p+1], a0f[0], &b1f[2]);
                mma_s8(Q[1][2*p+1], a0f[1], &b1f[2]);
                mma_s8(Q[0][2*p],   a1f[0], &b0f[0]);
                mma_s8(Q[1][2*p],   a1f[1], &b0f[0]);
                mma_s8(Q[0][2*p+1], a1f[0], &b0f[2]);
                mma_s8(Q[1][2*p+1], a1f[1], &b0f[2]);
            }
        }
    }

#pragma unroll
    for (int mt = 0; mt < 2; mt++) {
        const int r0 = bm + wm * 32 + mt * 16 + (lane >> 2);
        const float sa0 = sA[r0], sa1 = sA[r0 + 8];
#pragma unroll
        for (int nt = 0; nt < 4; nt++) {
            const int col = bn + wn * 32 + nt * 8 + (lane & 3) * 2;
            const float sb0 = sB[col], sb1 = sB[col + 1];
            const int* Pp = P[mt][nt];
            const int* Qp = Q[mt][nt];
            float c0 = sa0 * sb0 * ((float)Pp[0] + (float)Qp[0] * (1.f/128.f));
            float c1 = sa0 * sb1 * ((float)Pp[1] + (float)Qp[1] * (1.f/128.f));
            float c2 = sa1 * sb0 * ((float)Pp[2] + (float)Qp[2] * (1.f/128.f));
            float c3 = sa1 * sb1 * ((float)Pp[3] + (float)Qp[3] * (1.f/128.f));
            *(float2*)&C[(size_t)r0 * HH + col]       = make_float2(c0, c1);
            *(float2*)&C[(size_t)(r0 + 8) * HH + col] = make_float2(c2, c3);
        }
    }
}

// ===========================================================================
// Single-pass fused gating + scan with per-thread decoupled lookback (R12).
// ===========================================================================
__global__ __launch_bounds__(128) void scan_fused()
{
    extern __shared__ float sm[];             // [2][SC_CHUNK][128]
    float* smg = sm;
    float* smv = sm + SC_CHUNK * 128;
    const int thr = threadIdx.x;
    const int b = blockIdx.y;
    const int c = blockIdx.z;
    const int d = blockIdx.x * 128 + thr;
    const size_t base = ((size_t)(b * TT + c * SC_CHUNK)) * HH + d;

    float A = 1.f, Bv = 0.f;
#pragma unroll 4
    for (int t = 0; t < SC_CHUNK; t++) {
        const size_t o = base + (size_t)t * HH;
        float iv = g_gate[o];
        float fv = g_v[o];
        float u  = __expf(fminf(-fv, 30.f));
        float ve = __expf(fminf(-iv, 30.f));
        float pu = 1.f + u, pv = 1.f + ve;
        float r  = rcpa(pu * pv);
        float gate = pv * r;
        float vv = iv * pu * r * (1.f - gate);
        smg[t * 128 + thr] = gate;
        smv[t * 128 + thr] = vv;
        Bv = fmaf(gate, Bv, vv);
        A *= gate;
    }

    const size_t ci = ((size_t)(c * BB + b)) * HH + d;
    float carry = 0.f;
    if (c == 0) {
        ((volatile float*)g_inc)[ci] = Bv;
        __threadfence();
        ((volatile int*)g_flag)[ci] = 2;
    } else {
        ((volatile float*)g_aggA)[ci] = A;
        ((volatile float*)g_aggB)[ci] = Bv;
        __threadfence();
        ((volatile int*)g_flag)[ci] = 1;
        float Aac = 1.f, Bac = 0.f;
        for (int j = c - 1; j >= 0; j--) {
            const size_t cj = ((size_t)(j * BB + b)) * HH + d;
            int f;
            do { f = ((volatile int*)g_flag)[cj]; } while (f == 0);
            __threadfence();
            if (f == 2) {
                float hj = ((volatile float*)g_inc)[cj];
                carry = fmaf(Aac, hj, Bac);
                break;
            } else {
                float Aj = ((volatile float*)g_aggA)[cj];
                float Bj = ((volatile float*)g_aggB)[cj];
                Bac = fmaf(Aac, Bj, Bac);
                Aac = Aac * Aj;
            }
        }
        float inc = fmaf(A, carry, Bv);
        ((volatile float*)g_inc)[ci] = inc;
        __threadfence();
        ((volatile int*)g_flag)[ci] = 2;
    }

    float h = carry;
#pragma unroll 4
    for (int t = 0; t < SC_CHUNK; t++) {
        h = fmaf(smg[t * 128 + thr], h, smv[t * 128 + thr]);
        g_o[base + (size_t)t * HH] = h;
    }
}

// ---------------------------------------------------------------------------
// Gated RMSNorm; caches o in registers; quantizes output row directly.
// ---------------------------------------------------------------------------
__global__ __launch_bounds__(256) void norm_kernel(const float* __restrict__ w)
{
    const int m = blockIdx.x;
    const size_t row = (size_t)m * HH;
    const int t = threadIdx.x;
    float xs[8];
    float s = 0.0f;
#pragma unroll
    for (int it = 0; it < 2; it++) {
        int d4 = (it * 256 + t) * 4;
        float4 x = *(const float4*)&g_o[row + d4];
        xs[it*4+0] = x.x; xs[it*4+1] = x.y; xs[it*4+2] = x.z; xs[it*4+3] = x.w;
        s = fmaf(x.x, x.x, fmaf(x.y, x.y, fmaf(x.z, x.z, fmaf(x.w, x.w, s))));
    }
    __shared__ float red[8];
#pragma unroll
    for (int o = 16; o; o >>= 1) s += __shfl_xor_sync(0xffffffffu, s, o);
    if ((t & 31) == 0) red[t >> 5] = s;
    __syncthreads();
    if (t < 8) {
        float tt = red[t];
#pragma unroll
        for (int o = 4; o; o >>= 1) tt += __shfl_xor_sync(0xffu, tt, o);
        if (t == 0) red[0] = tt;
    }
    __syncthreads();
    const float rms = rsqrtf(red[0] / (float)HH + 1e-5f);

    float y[8];
    float mx = 0.f;
#pragma unroll
    for (int it = 0; it < 2; it++) {
        int d4 = (it * 256 + t) * 4;
        float4 gp = *(const float4*)&g_gp[row + d4];
        float4 wv = *(const float4*)&w[d4];
        y[it*4+0] = xs[it*4+0] * rms * wv.x * gp.x * sigf(gp.x);
        y[it*4+1] = xs[it*4+1] * rms * wv.y * gp.y * sigf(gp.y);
        y[it*4+2] = xs[it*4+2] * rms * wv.z * gp.z * sigf(gp.z);
        y[it*4+3] = xs[it*4+3] * rms * wv.w * gp.w * sigf(gp.w);
#pragma unroll
        for (int j = 0; j < 4; j++) mx = fmaxf(mx, fabsf(y[it*4+j]));
    }
    __syncthreads();
#pragma unroll
    for (int o = 16; o; o >>= 1) mx = fmaxf(mx, __shfl_xor_sync(0xffffffffu, mx, o));
    if ((t & 31) == 0) red[t >> 5] = mx;
    __syncthreads();
    if (t < 8) {
        float mm = red[t];
#pragma unroll
        for (int o = 4; o; o >>= 1) mm = fmaxf(mm, __shfl_xor_sync(0xffu, mm, o));
        if (t == 0) red[0] = mm;
    }
    __syncthreads();
    mx = red[0];
    const float sc = (mx > 0.f) ? mx / 127.f : 1.f;
    const float inv = 127.f * rcpa(fmaxf(mx, 1e-30f));
#pragma unroll
    for (int it = 0; it < 2; it++) {
        int d4 = (it * 256 + t) * 4;
        int a0[4], a1[4];
#pragma unroll
        for (int j = 0; j < 4; j++) {
            float q = y[it*4+j] * inv;
            float r0 = rintf(q);
            a0[j] = (int)r0;
            a1[j] = (int)rintf((q - r0) * 128.f);
        }
        *(uint32_t*)&g_X0[row + d4] = pack4(a0[0],a0[1],a0[2],a0[3]);
        *(uint32_t*)&g_X1[row + d4] = pack4(a1[0],a1[1],a1[2],a1[3]);
    }
    if (t == 0) g_sx[m] = sc;
}

// ---------------------------------------------------------------------------
// Launch
// ---------------------------------------------------------------------------
extern "C" void kernel_launch(void* const* d_in, const int* in_sizes, int n_in,
                              void* d_out, int out_size)
{
    const float* X  = (const float*)d_in[0];
    const float* Wi = (const float*)d_in[1];
    const float* Wf = (const float*)d_in[2];
    const float* Wg = (const float*)d_in[3];
    const float* Wo = (const float*)d_in[4];
    const float* gw = (const float*)d_in[5];
    float* out = (float*)d_out;

    cudaFuncSetAttribute(gemm_mma,  cudaFuncAttributeMaxDynamicSharedMemorySize, NSTG * STGB);
    cudaFuncSetAttribute(scan_fused, cudaFuncAttributeMaxDynamicSharedMemorySize,
                         2 * SC_CHUNK * 128 * (int)sizeof(float));

    int8_t *x0, *x1;
    float *sx;
    cudaGetSymbolAddress((void**)&x0,  g_X0);
    cudaGetSymbolAddress((void**)&x1,  g_X1);
    cudaGetSymbolAddress((void**)&sx,  g_sx);
    float *pi, *pf, *pg2;
    cudaGetSymbolAddress((void**)&pi,  g_gate);
    cudaGetSymbolAddress((void**)&pf,  g_v);
    cudaGetSymbolAddress((void**)&pg2, g_gp);

    // reset lookback flags (graph replay leaves them set)
    reset_flags<<<SC_N / 4 / 256, 256>>>();

    // quantize X and the 4 weights (2-limb int8, per-row scales)
    quant_x_kernel<<<MM, 256>>>(X);
    quant_w_kernel<<<dim3(HH, 4), 256>>>(Wi, Wf, Wg, Wo);

    // i/f/g projections (raw) via int8 tensor cores — CTA 128x64 tiles
    gemm_mma<<<dim3(HH/64, MM/128, 3), 256, NSTG*STGB>>>(x0, x1, sx, 0, pi, pf, pg2);

    // fused gating + linear recurrence (single pass, decoupled lookback)
    scan_fused<<<dim3(HH/128, BB, SC_NCH), 128,
                 2 * SC_CHUNK * 128 * sizeof(float)>>>();

    // gated RMSNorm -> quantized o (reuses g_X0/g_X1/g_sx)
    norm_kernel<<<MM, 256>>>(gw);

    // output projection -> d_out
    gemm_mma<<<dim3(HH/64, MM/128, 1), 256, NSTG*STGB>>>(x0, x1, sx, 3, out, out, out);
}

// round 14
// speedup vs baseline: 1.0025x; 1.0025x over previous
#include <cuda_runtime.h>
#include <cuda_bf16.h>
#include <cstdint>
#include <math.h>

// Problem constants (fixed: B=4, T=2048, H=2048)
#define BB 4
#define TT 2048
#define HH 2048
#define MM (BB*TT)              // 8192 rows

// Scan decomposition (single-pass, decoupled lookback)
#define SC_CHUNK 64
#define SC_NCH (TT/SC_CHUNK)    // 32 chunks
#define SC_N (BB*SC_NCH*HH)     // lookback slots

// ---------------------------------------------------------------------------
// Scratch (device globals — no runtime allocation allowed)
// ---------------------------------------------------------------------------
__device__ float g_gate[(size_t)MM*HH];   // raw i projection (GEMM out)
__device__ float g_v[(size_t)MM*HH];      // raw f projection (GEMM out)
__device__ float g_gp[(size_t)MM*HH];     // raw g projection
__device__ float g_o[(size_t)MM*HH];      // scan output
__device__ float g_aggA[SC_N];
__device__ float g_aggB[SC_N];
__device__ float g_inc[SC_N];
__device__ int   g_flag[SC_N];
// int8 2-limb quantized operands
__device__ int8_t g_X0[(size_t)MM*HH];
__device__ int8_t g_X1[(size_t)MM*HH];
__device__ int8_t g_W0[4][(size_t)HH*HH];
__device__ int8_t g_W1[4][(size_t)HH*HH];
__device__ float  g_sx[MM];
__device__ float  g_sw[4][HH];

__device__ __forceinline__ float rcpa(float x) {
    float y; asm("rcp.approx.f32 %0, %1;" : "=f"(y) : "f"(x)); return y;
}
__device__ __forceinline__ float sigf(float x) {
    return rcpa(1.0f + __expf(fminf(-x, 30.0f)));
}

// ---------------------------------------------------------------------------
// PTX helpers (sm_80-era -> valid on compute_100)
// ---------------------------------------------------------------------------
__device__ __forceinline__ uint32_t smem_u32(const void* p) {
    uint32_t a; asm("{ .reg .u64 t; cvta.to.shared.u64 t, %1; cvt.u32.u64 %0, t; }" : "=r"(a) : "l"(p));
    return a;
}
__device__ __forceinline__ void cp16(uint32_t saddr, const void* g) {
    asm volatile("cp.async.cg.shared.global [%0], [%1], 16;" :: "r"(saddr), "l"(g));
}
#define CP_COMMIT() asm volatile("cp.async.commit_group;" ::: "memory")
#define CP_WAIT0()  asm volatile("cp.async.wait_group 0;" ::: "memory")

__device__ __forceinline__ void ldm_x4(uint32_t a, uint32_t* r) {
    asm volatile("ldmatrix.sync.aligned.m8n8.x4.shared.b16 {%0,%1,%2,%3}, [%4];"
        : "=r"(r[0]), "=r"(r[1]), "=r"(r[2]), "=r"(r[3]) : "r"(a));
}
__device__ __forceinline__ void mma_s8(int* c, const uint32_t* a, const uint32_t* b) {
    asm volatile("mma.sync.aligned.m16n8k32.row.col.s32.s8.s8.s32 "
        "{%0,%1,%2,%3}, {%4,%5,%6,%7}, {%8,%9}, {%0,%1,%2,%3};"
        : "+r"(c[0]), "+r"(c[1]), "+r"(c[2]), "+r"(c[3])
        : "r"(a[0]), "r"(a[1]), "r"(a[2]), "r"(a[3]), "r"(b[0]), "r"(b[1]));
}

__device__ __forceinline__ uint32_t pack4(int b0, int b1, int b2, int b3) {
    return (uint32_t)(b0 & 255) | ((uint32_t)(b1 & 255) << 8)
         | ((uint32_t)(b2 & 255) << 16) | ((uint32_t)(b3 & 255) << 24);
}

// ---------------------------------------------------------------------------
// Lookback flag reset (graph replay leaves flags at 2)
// ---------------------------------------------------------------------------
__global__ __launch_bounds__(256) void reset_flags()
{
    const int i = blockIdx.x * 256 + threadIdx.x;
    ((int4*)g_flag)[i] = make_int4(0, 0, 0, 0);
}

// ---------------------------------------------------------------------------
// Row quantizer: x ~= s*(a0 + a1/128), a0,a1 int8, s = rowmax/127.
// ---------------------------------------------------------------------------
__device__ __forceinline__ void quant_row_body(
    const float* __restrict__ x, int8_t* __restrict__ d0,
    int8_t* __restrict__ d1, float* __restrict__ sarr, int row)
{
    const int t = threadIdx.x;
    float4 v0 = ((const float4*)x)[t*2];
    float4 v1 = ((const float4*)x)[t*2 + 1];
    float xs[8] = {v0.x, v0.y, v0.z, v0.w, v1.x, v1.y, v1.z, v1.w};
    float m = 0.f;
#pragma unroll
    for (int j = 0; j < 8; j++) m = fmaxf(m, fabsf(xs[j]));
    __shared__ float red[8];
#pragma unroll
    for (int o = 16; o; o >>= 1) m = fmaxf(m, __shfl_xor_sync(0xffffffffu, m, o));
    if ((t & 31) == 0) red[t >> 5] = m;
    __syncthreads();
    if (t < 8) {
        float mm = red[t];
#pragma unroll
        for (int o = 4; o; o >>= 1) mm = fmaxf(mm, __shfl_xor_sync(0xffu, mm, o));
        if (t == 0) red[0] = mm;
    }
    __syncthreads();
    m = red[0];
    const float s = (m > 0.f) ? m / 127.f : 1.f;
    const float inv = 127.f * rcpa(fmaxf(m, 1e-30f));
    int a0[8], a1[8];
#pragma unroll
    for (int j = 0; j < 8; j++) {
        float q = xs[j] * inv;
        float r0 = rintf(q);
        a0[j] = (int)r0;
        a1[j] = (int)rintf((q - r0) * 128.f);
    }
    ((uint2*)(d0 + (size_t)row * HH))[t] = make_uint2(pack4(a0[0],a0[1],a0[2],a0[3]), pack4(a0[4],a0[5],a0[6],a0[7]));
    ((uint2*)(d1 + (size_t)row * HH))[t] = make_uint2(pack4(a1[0],a1[1],a1[2],a1[3]), pack4(a1[4],a1[5],a1[6],a1[7]));
    if (t == 0) sarr[row] = s;
}

__global__ __launch_bounds__(256) void quant_x_kernel(const float* __restrict__ src)
{
    const int row = blockIdx.x;
    quant_row_body(src + (size_t)row * HH, g_X0, g_X1, g_sx, row);
}

__global__ __launch_bounds__(256) void quant_w_kernel(
    const float* __restrict__ s0, const float* __restrict__ s1,
    const float* __restrict__ s2, const float* __restrict__ s3)
{
    const int row = blockIdx.x;
    const int w = blockIdx.y;
    const float* src = (w == 0) ? s0 : (w == 1) ? s1 : (w == 2) ? s2 : s3;
    quant_row_body(src + (size_t)row * HH, g_W0[w], g_W1[w], g_sw[w], row);
}

// ===========================================================================
// 2-limb int8 GEMM on mma.sync m16n8k32 (R12 pipeline; rescheduled mainloop)
// CTA 128x64, warp tile 32x32, KC=64, 2-stage cp.async, 2 CTAs/SM.
// Inner loop: front-batched 8 LDSM per ks, then 24 MMAs in 3 groups of 8
// distinct accumulators (reuse distance 4 -> 8).
// ===========================================================================
#define KC 64
#define ROWB 80
#define A_MATB (128*ROWB)
#define B_MATB (64*ROWB)
#define STGB (2*A_MATB + 2*B_MATB)
#define OFF_A1 A_MATB
#define OFF_B0 (2*A_MATB)
#define OFF_B1 (2*A_MATB + B_MATB)
#define NKC (HH/KC)

__global__ __launch_bounds__(256, 2) void gemm_mma(
    const int8_t* __restrict__ x0, const int8_t* __restrict__ x1,
    const float* __restrict__ sA, int wbase,
    float* __restrict__ C0, float* __restrict__ C1, float* __restrict__ C2)
{
    extern __shared__ __align__(16) char smem[];
    const uint32_t sb = smem_u32(smem);
    const int tid = threadIdx.x, lane = tid & 31, wid = tid >> 5;
    const int wm = wid >> 1, wn = wid & 1;
    const int bm = blockIdx.y * 128, bn = blockIdx.x * 64;
    const int w = wbase + blockIdx.z;
    const int8_t* w0 = g_W0[w];
    const int8_t* w1 = g_W1[w];
    const float* sB = g_sw[w];
    float* C = (blockIdx.z == 0) ? C0 : (blockIdx.z == 1) ? C1 : C2;

    int P[2][4][4] = {}, Q[2][4][4] = {};

    auto load_stage = [&](int buf, int k0) {
        const uint32_t sbase = sb + buf * STGB;
#pragma unroll
        for (int i = 0; i < 6; i++) {
            int idx = i * 256 + tid;
            const int8_t* base; uint32_t moff; int row0, r, vv;
            if (i < 4) {
                int limb = idx >> 9;
                int rem = idx & 511;
                r = rem >> 2; vv = rem & 3;
                base = limb ? x1 : x0;
                moff = limb ? (uint32_t)OFF_A1 : 0u;
                row0 = bm;
            } else {
                int rem = idx - 1024;
                int limb = rem >> 8;
                rem &= 255;
                r = rem >> 2; vv = rem & 3;
                base = limb ? w1 : w0;
                moff = limb ? (uint32_t)OFF_B1 : (uint32_t)OFF_B0;
                row0 = bn;
            }
            cp16(sbase + moff + (uint32_t)(r * ROWB + vv * 16),
                 base + (size_t)(row0 + r) * HH + k0 + vv * 16);
        }
    };

    const uint32_t aRowOff = (uint32_t)((wm * 32 + (lane & 15)) * ROWB + (lane >> 4) * 16);
    const uint32_t bRowOff = (uint32_t)((wn * 32 + ((lane >> 4) << 3) + (lane & 7)) * ROWB
                                        + ((lane >> 3) & 1) * 16);

    load_stage(0, 0);
    CP_COMMIT();
    CP_WAIT0();
    __syncthreads();

    for (int c = 0; c < NKC; c++) {
        const int buf = c & 1;
        if (c + 1 < NKC) {
            load_stage(buf ^ 1, (c + 1) * KC);
            CP_COMMIT();
        }
        const uint32_t s0 = sb + buf * STGB;
#pragma unroll
        for (int ks = 0; ks < 2; ks++) {
            const uint32_t kOff = ks * 32;
            // ---- front-batched fragment loads: 4 A-LDSM + 4 B-LDSM ----
            uint32_t a0f[2][4], a1f[2][4];
            uint32_t b0f[2][4], b1f[2][4];
#pragma unroll
            for (int mt = 0; mt < 2; mt++) {
                ldm_x4(s0 + 0      + mt * 16 * ROWB + kOff + aRowOff, a0f[mt]);
                ldm_x4(s0 + OFF_A1 + mt * 16 * ROWB + kOff + aRowOff, a1f[mt]);
            }
#pragma unroll
            for (int p = 0; p < 2; p++) {
                ldm_x4(s0 + OFF_B0 + p * 16 * ROWB + kOff + bRowOff, b0f[p]);
                ldm_x4(s0 + OFF_B1 + p * 16 * ROWB + kOff + bRowOff, b1f[p]);
            }
            // ---- 24 MMAs in 3 groups of 8 distinct accumulators ----
            // group 1: P (a0*b0)
#pragma unroll
            for (int p = 0; p < 2; p++) {
                mma_s8(P[0][2*p],   a0f[0], &b0f[p][0]);
                mma_s8(P[1][2*p],   a0f[1], &b0f[p][0]);
                mma_s8(P[0][2*p+1], a0f[0], &b0f[p][2]);
                mma_s8(P[1][2*p+1], a0f[1], &b0f[p][2]);
            }
            // group 2: Q += a0*b1
#pragma unroll
            for (int p = 0; p < 2; p++) {
                mma_s8(Q[0][2*p],   a0f[0], &b1f[p][0]);
                mma_s8(Q[1][2*p],   a0f[1], &b1f[p][0]);
                mma_s8(Q[0][2*p+1], a0f[0], &b1f[p][2]);
                mma_s8(Q[1][2*p+1], a0f[1], &b1f[p][2]);
            }
            // group 3: Q += a1*b0  (reuse distance 8 from group 2)
#pragma unroll
            for (int p = 0; p < 2; p++) {
                mma_s8(Q[0][2*p],   a1f[0], &b0f[p][0]);
                mma_s8(Q[1][2*p],   a1f[1], &b0f[p][0]);
                mma_s8(Q[0][2*p+1], a1f[0], &b0f[p][2]);
                mma_s8(Q[1][2*p+1], a1f[1], &b0f[p][2]);
            }
        }
        if (c + 1 < NKC) {
            CP_WAIT0();
            __syncthreads();
        }
    }

#pragma unroll
    for (int mt = 0; mt < 2; mt++) {
        const int r0 = bm + wm * 32 + mt * 16 + (lane >> 2);
        const float sa0 = sA[r0], sa1 = sA[r0 + 8];
#pragma unroll
        for (int nt = 0; nt < 4; nt++) {
            const int col = bn + wn * 32 + nt * 8 + (lane & 3) * 2;
            const float sb0 = sB[col], sb1 = sB[col + 1];
            const int* Pp = P[mt][nt];
            const int* Qp = Q[mt][nt];
            float c0 = sa0 * sb0 * ((float)Pp[0] + (float)Qp[0] * (1.f/128.f));
            float c1 = sa0 * sb1 * ((float)Pp[1] + (float)Qp[1] * (1.f/128.f));
            float c2 = sa1 * sb0 * ((float)Pp[2] + (float)Qp[2] * (1.f/128.f));
            float c3 = sa1 * sb1 * ((float)Pp[3] + (float)Qp[3] * (1.f/128.f));
            *(float2*)&C[(size_t)r0 * HH + col]       = make_float2(c0, c1);
            *(float2*)&C[(size_t)(r0 + 8) * HH + col] = make_float2(c2, c3);
        }
    }
}

// ===========================================================================
// Single-pass fused gating + scan with per-thread decoupled lookback (R12).
// ===========================================================================
__global__ __launch_bounds__(128) void scan_fused()
{
    extern __shared__ float sm[];
    float* smg = sm;
    float* smv = sm + SC_CHUNK * 128;
    const int thr = threadIdx.x;
    const int b = blockIdx.y;
    const int c = blockIdx.z;
    const int d = blockIdx.x * 128 + thr;
    const size_t base = ((size_t)(b * TT + c * SC_CHUNK)) * HH + d;

    float A = 1.f, Bv = 0.f;
#pragma unroll 4
    for (int t = 0; t < SC_CHUNK; t++) {
        const size_t o = base + (size_t)t * HH;
        float iv = g_gate[o];
        float fv = g_v[o];
        float u  = __expf(fminf(-fv, 30.f));
        float ve = __expf(fminf(-iv, 30.f));
        float pu = 1.f + u, pv = 1.f + ve;
        float r  = rcpa(pu * pv);
        float gate = pv * r;
        float vv = iv * pu * r * (1.f - gate);
        smg[t * 128 + thr] = gate;
        smv[t * 128 + thr] = vv;
        Bv = fmaf(gate, Bv, vv);
        A *= gate;
    }

    const size_t ci = ((size_t)(c * BB + b)) * HH + d;
    float carry = 0.f;
    if (c == 0) {
        ((volatile float*)g_inc)[ci] = Bv;
        __threadfence();
        ((volatile int*)g_flag)[ci] = 2;
    } else {
        ((volatile float*)g_aggA)[ci] = A;
        ((volatile float*)g_aggB)[ci] = Bv;
        __threadfence();
        ((volatile int*)g_flag)[ci] = 1;
        float Aac = 1.f, Bac = 0.f;
        for (int j = c - 1; j >= 0; j--) {
            const size_t cj = ((size_t)(j * BB + b)) * HH + d;
            int f;
            do { f = ((volatile int*)g_flag)[cj]; } while (f == 0);
            __threadfence();
            if (f == 2) {
                float hj = ((volatile float*)g_inc)[cj];
                carry = fmaf(Aac, hj, Bac);
                break;
            } else {
                float Aj = ((volatile float*)g_aggA)[cj];
                float Bj = ((volatile float*)g_aggB)[cj];
                Bac = fmaf(Aac, Bj, Bac);
                Aac = Aac * Aj;
            }
        }
        float inc = fmaf(A, carry, Bv);
        ((volatile float*)g_inc)[ci] = inc;
        __threadfence();
        ((volatile int*)g_flag)[ci] = 2;
    }

    float h = carry;
#pragma unroll 4
    for (int t = 0; t < SC_CHUNK; t++) {
        h = fmaf(smg[t * 128 + thr], h, smv[t * 128 + thr]);
        g_o[base + (size_t)t * HH] = h;
    }
}

// ---------------------------------------------------------------------------
// Gated RMSNorm; caches o in registers; quantizes output row directly.
// ---------------------------------------------------------------------------
__global__ __launch_bounds__(256) void norm_kernel(const float* __restrict__ w)
{
    const int m = blockIdx.x;
    const size_t row = (size_t)m * HH;
    const int t = threadIdx.x;
    float xs[8];
    float s = 0.0f;
#pragma unroll
    for (int it = 0; it < 2; it++) {
        int d4 = (it * 256 + t) * 4;
        float4 x = *(const float4*)&g_o[row + d4];
        xs[it*4+0] = x.x; xs[it*4+1] = x.y; xs[it*4+2] = x.z; xs[it*4+3] = x.w;
        s = fmaf(x.x, x.x, fmaf(x.y, x.y, fmaf(x.z, x.z, fmaf(x.w, x.w, s))));
    }
    __shared__ float red[8];
#pragma unroll
    for (int o = 16; o; o >>= 1) s += __shfl_xor_sync(0xffffffffu, s, o);
    if ((t & 31) == 0) red[t >> 5] = s;
    __syncthreads();
    if (t < 8) {
        float tt = red[t];
#pragma unroll
        for (int o = 4; o; o >>= 1) tt += __shfl_xor_sync(0xffu, tt, o);
        if (t == 0) red[0] = tt;
    }
    __syncthreads();
    const float rms = rsqrtf(red[0] / (float)HH + 1e-5f);

    float y[8];
    float mx = 0.f;
#pragma unroll
    for (int it = 0; it < 2; it++) {
        int d4 = (it * 256 + t) * 4;
        float4 gp = *(const float4*)&g_gp[row + d4];
        float4 wv = *(const float4*)&w[d4];
        y[it*4+0] = xs[it*4+0] * rms * wv.x * gp.x * sigf(gp.x);
        y[it*4+1] = xs[it*4+1] * rms * wv.y * gp.y * sigf(gp.y);
        y[it*4+2] = xs[it*4+2] * rms * wv.z * gp.z * sigf(gp.z);
        y[it*4+3] = xs[it*4+3] * rms * wv.w * gp.w * sigf(gp.w);
#pragma unroll
        for (int j = 0; j < 4; j++) mx = fmaxf(mx, fabsf(y[it*4+j]));
    }
    __syncthreads();
#pragma unroll
    for (int o = 16; o; o >>= 1) mx = fmaxf(mx, __shfl_xor_sync(0xffffffffu, mx, o));
    if ((t & 31) == 0) red[t >> 5] = mx;
    __syncthreads();
    if (t < 8) {
        float mm = red[t];
#pragma unroll
        for (int o = 4; o; o >>= 1) mm = fmaxf(mm, __shfl_xor_sync(0xffu, mm, o));
        if (t == 0) red[0] = mm;
    }
    __syncthreads();
    mx = red[0];
    const float sc = (mx > 0.f) ? mx / 127.f : 1.f;
    const float inv = 127.f * rcpa(fmaxf(mx, 1e-30f));
#pragma unroll
    for (int it = 0; it < 2; it++) {
        int d4 = (it * 256 + t) * 4;
        int a0[4], a1[4];
#pragma unroll
        for (int j = 0; j < 4; j++) {
            float q = y[it*4+j] * inv;
            float r0 = rintf(q);
            a0[j] = (int)r0;
            a1[j] = (int)rintf((q - r0) * 128.f);
        }
        *(uint32_t*)&g_X0[row + d4] = pack4(a0[0],a0[1],a0[2],a0[3]);
        *(uint32_t*)&g_X1[row + d4] = pack4(a1[0],a1[1],a1[2],a1[3]);
    }
    if (t == 0) g_sx[m] = sc;
}

// ---------------------------------------------------------------------------
// Launch
// ---------------------------------------------------------------------------
extern "C" void kernel_launch(void* const* d_in, const int* in_sizes, int n_in,
                              void* d_out, int out_size)
{
    const float* X  = (const float*)d_in[0];
    const float* Wi = (const float*)d_in[1];
    const float* Wf = (const float*)d_in[2];
    const float* Wg = (const float*)d_in[3];
    const float* Wo = (const float*)d_in[4];
    const float* gw = (const float*)d_in[5];
    float* out = (float*)d_out;

    cudaFuncSetAttribute(gemm_mma,  cudaFuncAttributeMaxDynamicSharedMemorySize, 2 * STGB);
    cudaFuncSetAttribute(scan_fused, cudaFuncAttributeMaxDynamicSharedMemorySize,
                         2 * SC_CHUNK * 128 * (int)sizeof(float));

    int8_t *x0, *x1;
    float *sx;
    cudaGetSymbolAddress((void**)&x0,  g_X0);
    cudaGetSymbolAddress((void**)&x1,  g_X1);
    cudaGetSymbolAddress((void**)&sx,  g_sx);
    float *pi, *pf, *pg2;
    cudaGetSymbolAddress((void**)&pi,  g_gate);
    cudaGetSymbolAddress((void**)&pf,  g_v);
    cudaGetSymbolAddress((void**)&pg2, g_gp);

    // reset lookback flags (graph replay leaves them set)
    reset_flags<<<SC_N / 4 / 256, 256>>>();

    // quantize X and the 4 weights (2-limb int8, per-row scales)
    quant_x_kernel<<<MM, 256>>>(X);
    quant_w_kernel<<<dim3(HH, 4), 256>>>(Wi, Wf, Wg, Wo);

    // i/f/g projections (raw) via int8 tensor cores — CTA 128x64 tiles
    gemm_mma<<<dim3(HH/64, MM/128, 3), 256, 2*STGB>>>(x0, x1, sx, 0, pi, pf, pg2);

    // fused gating + linear recurrence (single pass, decoupled lookback)
    scan_fused<<<dim3(HH/128, BB, SC_NCH), 128,
                 2 * SC_CHUNK * 128 * sizeof(float)>>>();

    // gated RMSNorm -> quantized o (reuses g_X0/g_X1/g_sx)
    norm_kernel<<<MM, 256>>>(gw);

    // output projection -> d_out
    gemm_mma<<<dim3(HH/64, MM/128, 1), 256, 2*STGB>>>(x0, x1, sx, 3, out, out, out);
}

// round 16
// speedup vs baseline: 1.0850x; 1.0823x over previous
#include <cuda_runtime.h>
#include <cuda_bf16.h>
#include <cstdint>
#include <math.h>

// Problem constants (fixed: B=4, T=2048, H=2048)
#define BB 4
#define TT 2048
#define HH 2048
#define MM (BB*TT)              // 8192 rows

// Scan decomposition (single-pass, decoupled lookback)
#define SC_CHUNK 64
#define SC_NCH (TT/SC_CHUNK)    // 32 chunks
#define SC_N (BB*SC_NCH*HH)     // lookback slots (262144)

// ---------------------------------------------------------------------------
// Scratch (device globals — no runtime allocation allowed)
// ---------------------------------------------------------------------------
__device__ float g_gate[(size_t)MM*HH];   // raw i projection (GEMM out)
__device__ float g_v[(size_t)MM*HH];      // raw f projection (GEMM out)
__device__ float g_gp[(size_t)MM*HH];     // raw g projection
__device__ float g_o[(size_t)MM*HH];      // scan output
__device__ float g_aggA[SC_N];
__device__ float g_aggB[SC_N];
__device__ float g_inc[SC_N];
__device__ int   g_flag[SC_N];
// int8 2-limb quantized operands
__device__ int8_t g_X0[(size_t)MM*HH];
__device__ int8_t g_X1[(size_t)MM*HH];
__device__ int8_t g_W0[4][(size_t)HH*HH];
__device__ int8_t g_W1[4][(size_t)HH*HH];
__device__ float  g_sx[MM];
__device__ float  g_sw[4][HH];

__device__ __forceinline__ float rcpa(float x) {
    float y; asm("rcp.approx.f32 %0, %1;" : "=f"(y) : "f"(x)); return y;
}
__device__ __forceinline__ float sigf(float x) {
    return rcpa(1.0f + __expf(fminf(-x, 30.0f)));
}

// ---------------------------------------------------------------------------
// PTX helpers (sm_80-era -> valid on compute_100)
// ---------------------------------------------------------------------------
__device__ __forceinline__ uint32_t smem_u32(const void* p) {
    uint32_t a; asm("{ .reg .u64 t; cvta.to.shared.u64 t, %1; cvt.u32.u64 %0, t; }" : "=r"(a) : "l"(p));
    return a;
}
__device__ __forceinline__ void cp16(uint32_t saddr, const void* g) {
    asm volatile("cp.async.cg.shared.global [%0], [%1], 16;" :: "r"(saddr), "l"(g));
}
#define CP_COMMIT() asm volatile("cp.async.commit_group;" ::: "memory")
#define CP_WAIT0()  asm volatile("cp.async.wait_group 0;" ::: "memory")

__device__ __forceinline__ void ldm_x4(uint32_t a, uint32_t* r) {
    asm volatile("ldmatrix.sync.aligned.m8n8.x4.shared.b16 {%0,%1,%2,%3}, [%4];"
        : "=r"(r[0]), "=r"(r[1]), "=r"(r[2]), "=r"(r[3]) : "r"(a));
}
__device__ __forceinline__ void mma_s8(int* c, const uint32_t* a, const uint32_t* b) {
    asm volatile("mma.sync.aligned.m16n8k32.row.col.s32.s8.s8.s32 "
        "{%0,%1,%2,%3}, {%4,%5,%6,%7}, {%8,%9}, {%0,%1,%2,%3};"
        : "+r"(c[0]), "+r"(c[1]), "+r"(c[2]), "+r"(c[3])
        : "r"(a[0]), "r"(a[1]), "r"(a[2]), "r"(a[3]), "r"(b[0]), "r"(b[1]));
}
__device__ __forceinline__ void stg_cs2(float* p, float2 v) {
    asm volatile("st.global.cs.v2.f32 [%0], {%1, %2};" :: "l"(p), "f"(v.x), "f"(v.y) : "memory");
}

__device__ __forceinline__ uint32_t pack4(int b0, int b1, int b2, int b3) {
    return (uint32_t)(b0 & 255) | ((uint32_t)(b1 & 255) << 8)
         | ((uint32_t)(b2 & 255) << 16) | ((uint32_t)(b3 & 255) << 24);
}

// ---------------------------------------------------------------------------
// Row quantizer: x ~= s*(a0 + a1/128), a0,a1 int8, s = rowmax/127.
// ---------------------------------------------------------------------------
__device__ __forceinline__ void quant_row_body(
    const float* __restrict__ x, int8_t* __restrict__ d0,
    int8_t* __restrict__ d1, float* __restrict__ sarr, int row)
{
    const int t = threadIdx.x;
    float4 v0 = ((const float4*)x)[t*2];
    float4 v1 = ((const float4*)x)[t*2 + 1];
    float xs[8] = {v0.x, v0.y, v0.z, v0.w, v1.x, v1.y, v1.z, v1.w};
    float m = 0.f;
#pragma unroll
    for (int j = 0; j < 8; j++) m = fmaxf(m, fabsf(xs[j]));
    __shared__ float red[8];
#pragma unroll
    for (int o = 16; o; o >>= 1) m = fmaxf(m, __shfl_xor_sync(0xffffffffu, m, o));
    if ((t & 31) == 0) red[t >> 5] = m;
    __syncthreads();
    if (t < 8) {
        float mm = red[t];
#pragma unroll
        for (int o = 4; o; o >>= 1) mm = fmaxf(mm, __shfl_xor_sync(0xffu, mm, o));
        if (t == 0) red[0] = mm;
    }
    __syncthreads();
    m = red[0];
    const float s = (m > 0.f) ? m / 127.f : 1.f;
    const float inv = 127.f * rcpa(fmaxf(m, 1e-30f));
    int a0[8], a1[8];
#pragma unroll
    for (int j = 0; j < 8; j++) {
        float q = xs[j] * inv;
        float r0 = rintf(q);
        a0[j] = (int)r0;
        a1[j] = (int)rintf((q - r0) * 128.f);
    }
    ((uint2*)(d0 + (size_t)row * HH))[t] = make_uint2(pack4(a0[0],a0[1],a0[2],a0[3]), pack4(a0[4],a0[5],a0[6],a0[7]));
    ((uint2*)(d1 + (size_t)row * HH))[t] = make_uint2(pack4(a1[0],a1[1],a1[2],a1[3]), pack4(a1[4],a1[5],a1[6],a1[7]));
    if (t == 0) sarr[row] = s;
}

// One launch for X (y=0, 4 row-blocks) and all 4 weights (y=1..4).
// Also resets the scan lookback flags (GUARDED to SC_N — R15 bug fix).
__global__ __launch_bounds__(256) void quant_all_kernel(
    const float* __restrict__ X,
    const float* __restrict__ s0, const float* __restrict__ s1,
    const float* __restrict__ s2, const float* __restrict__ s3)
{
    const int y = blockIdx.y;
    if (y == 0) {
        // 4 consecutive X rows per block -> grid.x = MM/4 = HH
        for (int rr = 0; rr < 4; rr++) {
            const int row = blockIdx.x * 4 + rr;
            quant_row_body(X + (size_t)row * HH, g_X0, g_X1, g_sx, row);
            __syncthreads();
        }
        // flag reset: SC_N ints = SC_N/4 int4 = 65536 int4.
        // Blocks 0..127 each write 256 threads x 2 int4 = 512 int4.
        if (blockIdx.x < SC_N / 4 / 512) {
            const int base = (blockIdx.x * 256 + threadIdx.x) * 2;
            ((int4*)g_flag)[base]     = make_int4(0, 0, 0, 0);
            ((int4*)g_flag)[base + 1] = make_int4(0, 0, 0, 0);
        }
    } else {
        const int w = y - 1;
        const float* src = (w == 0) ? s0 : (w == 1) ? s1 : (w == 2) ? s2 : s3;
        quant_row_body(src + (size_t)blockIdx.x * HH, g_W0[w], g_W1[w], g_sw[w], blockIdx.x);
    }
}

// ===========================================================================
// 2-limb int8 GEMM on mma.sync m16n8k32
// CTA 128x64, warp tile 32x32, KC=128 (4 k32 steps), 2-stage cp.async,
// 2 CTAs/SM. Halves chunk count (16) to amortize per-chunk fixed overhead.
// C = sA[m]*sB[n]*(P + Q/128), P = a0w0, Q = a0w1 + a1w0 (a1w1 dropped).
// ===========================================================================
#define KC 128
#define ROWB 144               // 128B data + 16B pad: odd 16B-units -> conflict-free ldmatrix
#define A_MATB (128*ROWB)      // 18432 B per A limb
#define B_MATB (64*ROWB)       // 9216 B per B limb
#define STGB (2*A_MATB + 2*B_MATB)   // 55296 B per stage
#define OFF_A1 A_MATB
#define OFF_B0 (2*A_MATB)
#define OFF_B1 (2*A_MATB + B_MATB)
#define NKC (HH/KC)            // 16 k-iterations

__global__ __launch_bounds__(256, 2) void gemm_mma(
    const int8_t* __restrict__ x0, const int8_t* __restrict__ x1,
    const float* __restrict__ sA, int wbase, int streamC,
    float* __restrict__ C0, float* __restrict__ C1, float* __restrict__ C2)
{
    extern __shared__ __align__(16) char smem[];
    const uint32_t sb = smem_u32(smem);
    const int tid = threadIdx.x, lane = tid & 31, wid = tid >> 5;
    const int wm = wid >> 1, wn = wid & 1;
    const int bm = blockIdx.y * 128, bn = blockIdx.x * 64;
    const int w = wbase + blockIdx.z;
    const int8_t* w0 = g_W0[w];
    const int8_t* w1 = g_W1[w];
    const float* sB = g_sw[w];
    float* C = (blockIdx.z == 0) ? C0 : (blockIdx.z == 1) ? C1 : C2;

    int P[2][4][4] = {}, Q[2][4][4] = {};

    // stage loader: A 2 limbs 128x128B + B 2 limbs 64x128B = 3072 16B vecs, 12/thread
    auto load_stage = [&](int buf, int k0) {
        const uint32_t sbase = sb + buf * STGB;
#pragma unroll
        for (int i = 0; i < 12; i++) {
            int idx = i * 256 + tid;
            const int8_t* base; uint32_t moff; int row0, r, vv;
            if (i < 8) {                       // A limbs: 2 x 1024 vecs
                int limb = idx >> 10;
                int rem = idx & 1023;
                r = rem >> 3; vv = rem & 7;
                base = limb ? x1 : x0;
                moff = limb ? (uint32_t)OFF_A1 : 0u;
                row0 = bm;
            } else {                           // B limbs: 2 x 512 vecs
                int rem = idx - 2048;
                int limb = rem >> 9;
                rem &= 511;
                r = rem >> 3; vv = rem & 7;
                base = limb ? w1 : w0;
                moff = limb ? (uint32_t)OFF_B1 : (uint32_t)OFF_B0;
                row0 = bn;
            }
            cp16(sbase + moff + (uint32_t)(r * ROWB + vv * 16),
                 base + (size_t)(row0 + r) * HH + k0 + vv * 16);
        }
    };

    const uint32_t aRowOff = (uint32_t)((wm * 32 + (lane & 15)) * ROWB + (lane >> 4) * 16);
    const uint32_t bRowOff = (uint32_t)((wn * 32 + ((lane >> 4) << 3) + (lane & 7)) * ROWB
                                        + ((lane >> 3) & 1) * 16);

    load_stage(0, 0);
    CP_COMMIT();
    CP_WAIT0();
    __syncthreads();

    for (int c = 0; c < NKC; c++) {
        const int buf = c & 1;
        if (c + 1 < NKC) {
            load_stage(buf ^ 1, (c + 1) * KC);
            CP_COMMIT();
        }
        const uint32_t s0 = sb + buf * STGB;
#pragma unroll
        for (int ks = 0; ks < 4; ks++) {
            const uint32_t kOff = ks * 32;
            uint32_t a0f[2][4], a1f[2][4];
            uint32_t b0f[2][4], b1f[2][4];
#pragma unroll
            for (int mt = 0; mt < 2; mt++) {
                ldm_x4(s0 + 0      + mt * 16 * ROWB + kOff + aRowOff, a0f[mt]);
                ldm_x4(s0 + OFF_A1 + mt * 16 * ROWB + kOff + aRowOff, a1f[mt]);
            }
#pragma unroll
            for (int p = 0; p < 2; p++) {
                ldm_x4(s0 + OFF_B0 + p * 16 * ROWB + kOff + bRowOff, b0f[p]);
                ldm_x4(s0 + OFF_B1 + p * 16 * ROWB + kOff + bRowOff, b1f[p]);
            }
#pragma unroll
            for (int p = 0; p < 2; p++) {
                mma_s8(P[0][2*p],   a0f[0], &b0f[p][0]);
                mma_s8(P[1][2*p],   a0f[1], &b0f[p][0]);
                mma_s8(P[0][2*p+1], a0f[0], &b0f[p][2]);
                mma_s8(P[1][2*p+1], a0f[1], &b0f[p][2]);
            }
#pragma unroll
            for (int p = 0; p < 2; p++) {
                mma_s8(Q[0][2*p],   a0f[0], &b1f[p][0]);
                mma_s8(Q[1][2*p],   a0f[1], &b1f[p][0]);
                mma_s8(Q[0][2*p+1], a0f[0], &b1f[p][2]);
                mma_s8(Q[1][2*p+1], a0f[1], &b1f[p][2]);
            }
#pragma unroll
            for (int p = 0; p < 2; p++) {
                mma_s8(Q[0][2*p],   a1f[0], &b0f[p][0]);
                mma_s8(Q[1][2*p],   a1f[1], &b0f[p][0]);
                mma_s8(Q[0][2*p+1], a1f[0], &b0f[p][2]);
                mma_s8(Q[1][2*p+1], a1f[1], &b0f[p][2]);
            }
        }
        if (c + 1 < NKC) {
            CP_WAIT0();
            __syncthreads();
        }
    }

#pragma unroll
    for (int mt = 0; mt < 2; mt++) {
        const int r0 = bm + wm * 32 + mt * 16 + (lane >> 2);
        const float sa0 = sA[r0], sa1 = sA[r0 + 8];
#pragma unroll
        for (int nt = 0; nt < 4; nt++) {
            const int col = bn + wn * 32 + nt * 8 + (lane & 3) * 2;
            const float sb0 = sB[col], sb1 = sB[col + 1];
            const int* Pp = P[mt][nt];
            const int* Qp = Q[mt][nt];
            float c0 = sa0 * sb0 * ((float)Pp[0] + (float)Qp[0] * (1.f/128.f));
            float c1 = sa0 * sb1 * ((float)Pp[1] + (float)Qp[1] * (1.f/128.f));
            float c2 = sa1 * sb0 * ((float)Pp[2] + (float)Qp[2] * (1.f/128.f));
            float c3 = sa1 * sb1 * ((float)Pp[3] + (float)Qp[3] * (1.f/128.f));
            if (streamC) {     // d_out is never re-read: streaming stores
                stg_cs2(&C[(size_t)r0 * HH + col],       make_float2(c0, c1));
                stg_cs2(&C[(size_t)(r0 + 8) * HH + col], make_float2(c2, c3));
            } else {
                *(float2*)&C[(size_t)r0 * HH + col]       = make_float2(c0, c1);
                *(float2*)&C[(size_t)(r0 + 8) * HH + col] = make_float2(c2, c3);
            }
        }
    }
}

// ===========================================================================
// Single-pass fused gating + scan with per-thread decoupled lookback (R12).
// ===========================================================================
__global__ __launch_bounds__(128) void scan_fused()
{
    extern __shared__ float sm[];
    float* smg = sm;
    float* smv = sm + SC_CHUNK * 128;
    const int thr = threadIdx.x;
    const int b = blockIdx.y;
    const int c = blockIdx.z;
    const int d = blockIdx.x * 128 + thr;
    const size_t base = ((size_t)(b * TT + c * SC_CHUNK)) * HH + d;

    float A = 1.f, Bv = 0.f;
#pragma unroll 4
    for (int t = 0; t < SC_CHUNK; t++) {
        const size_t o = base + (size_t)t * HH;
        float iv = g_gate[o];
        float fv = g_v[o];
        float u  = __expf(fminf(-fv, 30.f));
        float ve = __expf(fminf(-iv, 30.f));
        float pu = 1.f + u, pv = 1.f + ve;
        float r  = rcpa(pu * pv);
        float gate = pv * r;
        float vv = iv * pu * r * (1.f - gate);
        smg[t * 128 + thr] = gate;
        smv[t * 128 + thr] = vv;
        Bv = fmaf(gate, Bv, vv);
        A *= gate;
    }

    const size_t ci = ((size_t)(c * BB + b)) * HH + d;
    float carry = 0.f;
    if (c == 0) {
        ((volatile float*)g_inc)[ci] = Bv;
        __threadfence();
        ((volatile int*)g_flag)[ci] = 2;
    } else {
        ((volatile float*)g_aggA)[ci] = A;
        ((volatile float*)g_aggB)[ci] = Bv;
        __threadfence();
        ((volatile int*)g_flag)[ci] = 1;
        float Aac = 1.f, Bac = 0.f;
        for (int j = c - 1; j >= 0; j--) {
            const size_t cj = ((size_t)(j * BB + b)) * HH + d;
            int f;
            do { f = ((volatile int*)g_flag)[cj]; } while (f == 0);
            __threadfence();
            if (f == 2) {
                float hj = ((volatile float*)g_inc)[cj];
                carry = fmaf(Aac, hj, Bac);
                break;
            } else {
                float Aj = ((volatile float*)g_aggA)[cj];
                float Bj = ((volatile float*)g_aggB)[cj];
                Bac = fmaf(Aac, Bj, Bac);
                Aac = Aac * Aj;
            }
        }
        float inc = fmaf(A, carry, Bv);
        ((volatile float*)g_inc)[ci] = inc;
        __threadfence();
        ((volatile int*)g_flag)[ci] = 2;
    }

    float h = carry;
#pragma unroll 4
    for (int t = 0; t < SC_CHUNK; t++) {
        h = fmaf(smg[t * 128 + thr], h, smv[t * 128 + thr]);
        g_o[base + (size_t)t * HH] = h;
    }
}

// ---------------------------------------------------------------------------
// Gated RMSNorm; caches o in registers; quantizes output row directly.
// ---------------------------------------------------------------------------
__global__ __launch_bounds__(256) void norm_kernel(const float* __restrict__ w)
{
    const int m = blockIdx.x;
    const size_t row = (size_t)m * HH;
    const int t = threadIdx.x;
    float xs[8];
    float s = 0.0f;
#pragma unroll
    for (int it = 0; it < 2; it++) {
        int d4 = (it * 256 + t) * 4;
        float4 x = *(const float4*)&g_o[row + d4];
        xs[it*4+0] = x.x; xs[it*4+1] = x.y; xs[it*4+2] = x.z; xs[it*4+3] = x.w;
        s = fmaf(x.x, x.x, fmaf(x.y, x.y, fmaf(x.z, x.z, fmaf(x.w, x.w, s))));
    }
    __shared__ float red[8];
#pragma unroll
    for (int o = 16; o; o >>= 1) s += __shfl_xor_sync(0xffffffffu, s, o);
    if ((t & 31) == 0) red[t >> 5] = s;
    __syncthreads();
    if (t < 8) {
        float tt = red[t];
#pragma unroll
        for (int o = 4; o; o >>= 1) tt += __shfl_xor_sync(0xffu, tt, o);
        if (t == 0) red[0] = tt;
    }
    __syncthreads();
    const float rms = rsqrtf(red[0] / (float)HH + 1e-5f);

    float y[8];
    float mx = 0.f;
#pragma unroll
    for (int it = 0; it < 2; it++) {
        int d4 = (it * 256 + t) * 4;
        float4 gp = *(const float4*)&g_gp[row + d4];
        float4 wv = *(const float4*)&w[d4];
        y[it*4+0] = xs[it*4+0] * rms * wv.x * gp.x * sigf(gp.x);
        y[it*4+1] = xs[it*4+1] * rms * wv.y * gp.y * sigf(gp.y);
        y[it*4+2] = xs[it*4+2] * rms * wv.z * gp.z * sigf(gp.z);
        y[it*4+3] = xs[it*4+3] * rms * wv.w * gp.w * sigf(gp.w);
#pragma unroll
        for (int j = 0; j < 4; j++) mx = fmaxf(mx, fabsf(y[it*4+j]));
    }
    __syncthreads();
#pragma unroll
    for (int o = 16; o; o >>= 1) mx = fmaxf(mx, __shfl_xor_sync(0xffffffffu, mx, o));
    if ((t & 31) == 0) red[t >> 5] = mx;
    __syncthreads();
    if (t < 8) {
        float mm = red[t];
#pragma unroll
        for (int o = 4; o; o >>= 1) mm = fmaxf(mm, __shfl_xor_sync(0xffu, mm, o));
        if (t == 0) red[0] = mm;
    }
    __syncthreads();
    mx = red[0];
    const float sc = (mx > 0.f) ? mx / 127.f : 1.f;
    const float inv = 127.f * rcpa(fmaxf(mx, 1e-30f));
#pragma unroll
    for (int it = 0; it < 2; it++) {
        int d4 = (it * 256 + t) * 4;
        int a0[4], a1[4];
#pragma unroll
        for (int j = 0; j < 4; j++) {
            float q = y[it*4+j] * inv;
            float r0 = rintf(q);
            a0[j] = (int)r0;
            a1[j] = (int)rintf((q - r0) * 128.f);
        }
        *(uint32_t*)&g_X0[row + d4] = pack4(a0[0],a0[1],a0[2],a0[3]);
        *(uint32_t*)&g_X1[row + d4] = pack4(a1[0],a1[1],a1[2],a1[3]);
    }
    if (t == 0) g_sx[m] = sc;
}

// ---------------------------------------------------------------------------
// Launch
// ---------------------------------------------------------------------------
extern "C" void kernel_launch(void* const* d_in, const int* in_sizes, int n_in,
                              void* d_out, int out_size)
{
    const float* X  = (const float*)d_in[0];
    const float* Wi = (const float*)d_in[1];
    const float* Wf = (const float*)d_in[2];
    const float* Wg = (const float*)d_in[3];
    const float* Wo = (const float*)d_in[4];
    const float* gw = (const float*)d_in[5];
    float* out = (float*)d_out;

    cudaFuncSetAttribute(gemm_mma,  cudaFuncAttributeMaxDynamicSharedMemorySize, 2 * STGB);
    cudaFuncSetAttribute(scan_fused, cudaFuncAttributeMaxDynamicSharedMemorySize,
                         2 * SC_CHUNK * 128 * (int)sizeof(float));

    int8_t *x0, *x1;
    float *sx;
    cudaGetSymbolAddress((void**)&x0,  g_X0);
    cudaGetSymbolAddress((void**)&x1,  g_X1);
    cudaGetSymbolAddress((void**)&sx,  g_sx);
    float *pi, *pf, *pg2;
    cudaGetSymbolAddress((void**)&pi,  g_gate);
    cudaGetSymbolAddress((void**)&pf,  g_v);
    cudaGetSymbolAddress((void**)&pg2, g_gp);

    // quantize X + 4 weights (single launch); also resets lookback flags
    quant_all_kernel<<<dim3(HH, 5), 256>>>(X, Wi, Wf, Wg, Wo);

    // i/f/g projections (raw) via int8 tensor cores — CTA 128x64, KC=128
    gemm_mma<<<dim3(HH/64, MM/128, 3), 256, 2*STGB>>>(x0, x1, sx, 0, 0, pi, pf, pg2);

    // fused gating + linear recurrence (single pass, decoupled lookback)
    scan_fused<<<dim3(HH/128, BB, SC_NCH), 128,
                 2 * SC_CHUNK * 128 * sizeof(float)>>>();

    // gated RMSNorm -> quantized o (reuses g_X0/g_X1/g_sx)
    norm_kernel<<<MM, 256>>>(gw);

    // output projection -> d_out (streaming stores)
    gemm_mma<<<dim3(HH/64, MM/128, 1), 256, 2*STGB>>>(x0, x1, sx, 3, 1, out, out, out);
}

// round 17
// speedup vs baseline: 1.1033x; 1.0168x over previous
#include <cuda_runtime.h>
#include <cuda_bf16.h>
#include <cstdint>
#include <math.h>

// Problem constants (fixed: B=4, T=2048, H=2048)
#define BB 4
#define TT 2048
#define HH 2048
#define MM (BB*TT)              // 8192 rows

// Scan decomposition (single-pass, decoupled lookback)
#define SC_CHUNK 64
#define SC_NCH (TT/SC_CHUNK)    // 32 chunks
#define SC_N (BB*SC_NCH*HH)     // lookback slots (262144)

// ---------------------------------------------------------------------------
// Scratch (device globals — no runtime allocation allowed)
// ---------------------------------------------------------------------------
__device__ float g_gate[(size_t)MM*HH];   // raw i projection (GEMM out)
__device__ float g_v[(size_t)MM*HH];      // raw f projection (GEMM out)
__device__ float g_gp[(size_t)MM*HH];     // raw g projection
__device__ float g_o[(size_t)MM*HH];      // scan output
__device__ float g_aggA[SC_N];
__device__ float g_aggB[SC_N];
__device__ float g_inc[SC_N];
__device__ int   g_flag[SC_N];
// int8 2-limb quantized operands
__device__ int8_t g_X0[(size_t)MM*HH];
__device__ int8_t g_X1[(size_t)MM*HH];
__device__ int8_t g_W0[4][(size_t)HH*HH];
__device__ int8_t g_W1[4][(size_t)HH*HH];
__device__ float  g_sx[MM];
__device__ float  g_sw[4][HH];

__device__ __forceinline__ float rcpa(float x) {
    float y; asm("rcp.approx.f32 %0, %1;" : "=f"(y) : "f"(x)); return y;
}
__device__ __forceinline__ float sigf(float x) {
    return rcpa(1.0f + __expf(fminf(-x, 30.0f)));
}

// ---------------------------------------------------------------------------
// PTX helpers (sm_80-era -> valid on compute_100)
// ---------------------------------------------------------------------------
__device__ __forceinline__ uint32_t smem_u32(const void* p) {
    uint32_t a; asm("{ .reg .u64 t; cvta.to.shared.u64 t, %1; cvt.u32.u64 %0, t; }" : "=r"(a) : "l"(p));
    return a;
}
__device__ __forceinline__ void cp16(uint32_t saddr, const void* g) {
    asm volatile("cp.async.cg.shared.global [%0], [%1], 16;" :: "r"(saddr), "l"(g));
}
#define CP_COMMIT() asm volatile("cp.async.commit_group;" ::: "memory")
#define CP_WAIT0()  asm volatile("cp.async.wait_group 0;" ::: "memory")

__device__ __forceinline__ void ldm_x4(uint32_t a, uint32_t* r) {
    asm volatile("ldmatrix.sync.aligned.m8n8.x4.shared.b16 {%0,%1,%2,%3}, [%4];"
        : "=r"(r[0]), "=r"(r[1]), "=r"(r[2]), "=r"(r[3]) : "r"(a));
}
__device__ __forceinline__ void mma_s8(int* c, const uint32_t* a, const uint32_t* b) {
    asm volatile("mma.sync.aligned.m16n8k32.row.col.s32.s8.s8.s32 "
        "{%0,%1,%2,%3}, {%4,%5,%6,%7}, {%8,%9}, {%0,%1,%2,%3};"
        : "+r"(c[0]), "+r"(c[1]), "+r"(c[2]), "+r"(c[3])
        : "r"(a[0]), "r"(a[1]), "r"(a[2]), "r"(a[3]), "r"(b[0]), "r"(b[1]));
}
__device__ __forceinline__ void stg_cs2(float* p, float2 v) {
    asm volatile("st.global.cs.v2.f32 [%0], {%1, %2};" :: "l"(p), "f"(v.x), "f"(v.y) : "memory");
}

__device__ __forceinline__ uint32_t pack4(int b0, int b1, int b2, int b3) {
    return (uint32_t)(b0 & 255) | ((uint32_t)(b1 & 255) << 8)
         | ((uint32_t)(b2 & 255) << 16) | ((uint32_t)(b3 & 255) << 24);
}

// ---------------------------------------------------------------------------
// Row quantizer: x ~= s*(a0 + a1/128), a0,a1 int8, s = rowmax/127.
// ---------------------------------------------------------------------------
__device__ __forceinline__ void quant_row_body(
    const float* __restrict__ x, int8_t* __restrict__ d0,
    int8_t* __restrict__ d1, float* __restrict__ sarr, int row)
{
    const int t = threadIdx.x;
    float4 v0 = ((const float4*)x)[t*2];
    float4 v1 = ((const float4*)x)[t*2 + 1];
    float xs[8] = {v0.x, v0.y, v0.z, v0.w, v1.x, v1.y, v1.z, v1.w};
    float m = 0.f;
#pragma unroll
    for (int j = 0; j < 8; j++) m = fmaxf(m, fabsf(xs[j]));
    __shared__ float red[8];
#pragma unroll
    for (int o = 16; o; o >>= 1) m = fmaxf(m, __shfl_xor_sync(0xffffffffu, m, o));
    if ((t & 31) == 0) red[t >> 5] = m;
    __syncthreads();
    if (t < 8) {
        float mm = red[t];
#pragma unroll
        for (int o = 4; o; o >>= 1) mm = fmaxf(mm, __shfl_xor_sync(0xffu, mm, o));
        if (t == 0) red[0] = mm;
    }
    __syncthreads();
    m = red[0];
    const float s = (m > 0.f) ? m / 127.f : 1.f;
    const float inv = 127.f * rcpa(fmaxf(m, 1e-30f));
    int a0[8], a1[8];
#pragma unroll
    for (int j = 0; j < 8; j++) {
        float q = xs[j] * inv;
        float r0 = rintf(q);
        a0[j] = (int)r0;
        a1[j] = (int)rintf((q - r0) * 128.f);
    }
    ((uint2*)(d0 + (size_t)row * HH))[t] = make_uint2(pack4(a0[0],a0[1],a0[2],a0[3]), pack4(a0[4],a0[5],a0[6],a0[7]));
    ((uint2*)(d1 + (size_t)row * HH))[t] = make_uint2(pack4(a1[0],a1[1],a1[2],a1[3]), pack4(a1[4],a1[5],a1[6],a1[7]));
    if (t == 0) sarr[row] = s;
}

// One launch for X (y=0, 4 row-blocks) and all 4 weights (y=1..4).
// Also resets the scan lookback flags (guarded to SC_N).
__global__ __launch_bounds__(256) void quant_all_kernel(
    const float* __restrict__ X,
    const float* __restrict__ s0, const float* __restrict__ s1,
    const float* __restrict__ s2, const float* __restrict__ s3)
{
    const int y = blockIdx.y;
    if (y == 0) {
        for (int rr = 0; rr < 4; rr++) {
            const int row = blockIdx.x * 4 + rr;
            quant_row_body(X + (size_t)row * HH, g_X0, g_X1, g_sx, row);
            __syncthreads();
        }
        if (blockIdx.x < SC_N / 4 / 512) {
            const int base = (blockIdx.x * 256 + threadIdx.x) * 2;
            ((int4*)g_flag)[base]     = make_int4(0, 0, 0, 0);
            ((int4*)g_flag)[base + 1] = make_int4(0, 0, 0, 0);
        }
    } else {
        const int w = y - 1;
        const float* src = (w == 0) ? s0 : (w == 1) ? s1 : (w == 2) ? s2 : s3;
        quant_row_body(src + (size_t)blockIdx.x * HH, g_W0[w], g_W1[w], g_sw[w], blockIdx.x);
    }
}

// ===========================================================================
// 2-limb int8 GEMM on mma.sync m16n8k32
// CTA **128x128**, 512 threads (4x4 warp grid, 32x32 tiles), KC=128,
// 2-stage cp.async, 1 CTA/SM (full RF: 512 thr x 128 regs).
// Same warps/SMSP (4) and accum regs/thread (64) as R16; halves L2 traffic
// and per-chunk sync overhead per output element.
// ===========================================================================
#define KC 128
#define ROWB 144               // 128B data + 16B pad: conflict-free ldmatrix
#define A_MATB (128*ROWB)      // 18432 B per A limb
#define B_MATB (128*ROWB)      // 18432 B per B limb (128 rows now)
#define STGB (2*A_MATB + 2*B_MATB)   // 73728 B per stage
#define OFF_A1 A_MATB
#define OFF_B0 (2*A_MATB)
#define OFF_B1 (2*A_MATB + B_MATB)
#define NKC (HH/KC)            // 16 k-iterations
#define NTHR 512

__global__ __launch_bounds__(NTHR, 1) void gemm_mma(
    const int8_t* __restrict__ x0, const int8_t* __restrict__ x1,
    const float* __restrict__ sA, int wbase, int streamC,
    float* __restrict__ C0, float* __restrict__ C1, float* __restrict__ C2)
{
    extern __shared__ __align__(16) char smem[];
    const uint32_t sb = smem_u32(smem);
    const int tid = threadIdx.x, lane = tid & 31, wid = tid >> 5;
    const int wm = wid >> 2, wn = wid & 3;           // 4x4 warp grid, 32x32 tiles
    const int bm = blockIdx.y * 128, bn = blockIdx.x * 128;
    const int w = wbase + blockIdx.z;
    const int8_t* w0 = g_W0[w];
    const int8_t* w1 = g_W1[w];
    const float* sB = g_sw[w];
    float* C = (blockIdx.z == 0) ? C0 : (blockIdx.z == 1) ? C1 : C2;

    int P[2][4][4] = {}, Q[2][4][4] = {};   // 64 accum regs/thread

    // stage loader: A 2x1024 vecs + B 2x1024 vecs = 4096, 8 per thread
    auto load_stage = [&](int buf, int k0) {
        const uint32_t sbase = sb + buf * STGB;
#pragma unroll
        for (int i = 0; i < 8; i++) {
            int idx = i * NTHR + tid;
            const int8_t* base; uint32_t moff; int row0;
            int rem2 = idx & 2047;
            int limb = rem2 >> 10;
            int rem = rem2 & 1023;
            int r = rem >> 3, vv = rem & 7;
            if (idx < 2048) {                  // A limbs
                base = limb ? x1 : x0;
                moff = limb ? (uint32_t)OFF_A1 : 0u;
                row0 = bm;
            } else {                           // B limbs
                base = limb ? w1 : w0;
                moff = limb ? (uint32_t)OFF_B1 : (uint32_t)OFF_B0;
                row0 = bn;
            }
            cp16(sbase + moff + (uint32_t)(r * ROWB + vv * 16),
                 base + (size_t)(row0 + r) * HH + k0 + vv * 16);
        }
    };

    const uint32_t aRowOff = (uint32_t)((wm * 32 + (lane & 15)) * ROWB + (lane >> 4) * 16);
    const uint32_t bRowOff = (uint32_t)((wn * 32 + ((lane >> 4) << 3) + (lane & 7)) * ROWB
                                        + ((lane >> 3) & 1) * 16);

    load_stage(0, 0);
    CP_COMMIT();
    CP_WAIT0();
    __syncthreads();

    for (int c = 0; c < NKC; c++) {
        const int buf = c & 1;
        if (c + 1 < NKC) {
            load_stage(buf ^ 1, (c + 1) * KC);
            CP_COMMIT();
        }
        const uint32_t s0 = sb + buf * STGB;
#pragma unroll
        for (int ks = 0; ks < 4; ks++) {
            const uint32_t kOff = ks * 32;
            uint32_t a0f[2][4], a1f[2][4];
            uint32_t b0f[2][4], b1f[2][4];
#pragma unroll
            for (int mt = 0; mt < 2; mt++) {
                ldm_x4(s0 + 0      + mt * 16 * ROWB + kOff + aRowOff, a0f[mt]);
                ldm_x4(s0 + OFF_A1 + mt * 16 * ROWB + kOff + aRowOff, a1f[mt]);
            }
#pragma unroll
            for (int p = 0; p < 2; p++) {
                ldm_x4(s0 + OFF_B0 + p * 16 * ROWB + kOff + bRowOff, b0f[p]);
                ldm_x4(s0 + OFF_B1 + p * 16 * ROWB + kOff + bRowOff, b1f[p]);
            }
#pragma unroll
            for (int p = 0; p < 2; p++) {
                mma_s8(P[0][2*p],   a0f[0], &b0f[p][0]);
                mma_s8(P[1][2*p],   a0f[1], &b0f[p][0]);
                mma_s8(P[0][2*p+1], a0f[0], &b0f[p][2]);
                mma_s8(P[1][2*p+1], a0f[1], &b0f[p][2]);
            }
#pragma unroll
            for (int p = 0; p < 2; p++) {
                mma_s8(Q[0][2*p],   a0f[0], &b1f[p][0]);
                mma_s8(Q[1][2*p],   a0f[1], &b1f[p][0]);
                mma_s8(Q[0][2*p+1], a0f[0], &b1f[p][2]);
                mma_s8(Q[1][2*p+1], a0f[1], &b1f[p][2]);
            }
#pragma unroll
            for (int p = 0; p < 2; p++) {
                mma_s8(Q[0][2*p],   a1f[0], &b0f[p][0]);
                mma_s8(Q[1][2*p],   a1f[1], &b0f[p][0]);
                mma_s8(Q[0][2*p+1], a1f[0], &b0f[p][2]);
                mma_s8(Q[1][2*p+1], a1f[1], &b0f[p][2]);
            }
        }
        if (c + 1 < NKC) {
            CP_WAIT0();
            __syncthreads();
        }
    }

#pragma unroll
    for (int mt = 0; mt < 2; mt++) {
        const int r0 = bm + wm * 32 + mt * 16 + (lane >> 2);
        const float sa0 = sA[r0], sa1 = sA[r0 + 8];
#pragma unroll
        for (int nt = 0; nt < 4; nt++) {
            const int col = bn + wn * 32 + nt * 8 + (lane & 3) * 2;
            const float sb0 = sB[col], sb1 = sB[col + 1];
            const int* Pp = P[mt][nt];
            const int* Qp = Q[mt][nt];
            float c0 = sa0 * sb0 * ((float)Pp[0] + (float)Qp[0] * (1.f/128.f));
            float c1 = sa0 * sb1 * ((float)Pp[1] + (float)Qp[1] * (1.f/128.f));
            float c2 = sa1 * sb0 * ((float)Pp[2] + (float)Qp[2] * (1.f/128.f));
            float c3 = sa1 * sb1 * ((float)Pp[3] + (float)Qp[3] * (1.f/128.f));
            if (streamC) {
                stg_cs2(&C[(size_t)r0 * HH + col],       make_float2(c0, c1));
                stg_cs2(&C[(size_t)(r0 + 8) * HH + col], make_float2(c2, c3));
            } else {
                *(float2*)&C[(size_t)r0 * HH + col]       = make_float2(c0, c1);
                *(float2*)&C[(size_t)(r0 + 8) * HH + col] = make_float2(c2, c3);
            }
        }
    }
}

// ===========================================================================
// Single-pass fused gating + scan with per-thread decoupled lookback (R12).
// ===========================================================================
__global__ __launch_bounds__(128) void scan_fused()
{
    extern __shared__ float sm[];
    float* smg = sm;
    float* smv = sm + SC_CHUNK * 128;
    const int thr = threadIdx.x;
    const int b = blockIdx.y;
    const int c = blockIdx.z;
    const int d = blockIdx.x * 128 + thr;
    const size_t base = ((size_t)(b * TT + c * SC_CHUNK)) * HH + d;

    float A = 1.f, Bv = 0.f;
#pragma unroll 4
    for (int t = 0; t < SC_CHUNK; t++) {
        const size_t o = base + (size_t)t * HH;
        float iv = g_gate[o];
        float fv = g_v[o];
        float u  = __expf(fminf(-fv, 30.f));
        float ve = __expf(fminf(-iv, 30.f));
        float pu = 1.f + u, pv = 1.f + ve;
        float r  = rcpa(pu * pv);
        float gate = pv * r;
        float vv = iv * pu * r * (1.f - gate);
        smg[t * 128 + thr] = gate;
        smv[t * 128 + thr] = vv;
        Bv = fmaf(gate, Bv, vv);
        A *= gate;
    }

    const size_t ci = ((size_t)(c * BB + b)) * HH + d;
    float carry = 0.f;
    if (c == 0) {
        ((volatile float*)g_inc)[ci] = Bv;
        __threadfence();
        ((volatile int*)g_flag)[ci] = 2;
    } else {
        ((volatile float*)g_aggA)[ci] = A;
        ((volatile float*)g_aggB)[ci] = Bv;
        __threadfence();
        ((volatile int*)g_flag)[ci] = 1;
        float Aac = 1.f, Bac = 0.f;
        for (int j = c - 1; j >= 0; j--) {
            const size_t cj = ((size_t)(j * BB + b)) * HH + d;
            int f;
            do { f = ((volatile int*)g_flag)[cj]; } while (f == 0);
            __threadfence();
            if (f == 2) {
                float hj = ((volatile float*)g_inc)[cj];
                carry = fmaf(Aac, hj, Bac);
                break;
            } else {
                float Aj = ((volatile float*)g_aggA)[cj];
                float Bj = ((volatile float*)g_aggB)[cj];
                Bac = fmaf(Aac, Bj, Bac);
                Aac = Aac * Aj;
            }
        }
        float inc = fmaf(A, carry, Bv);
        ((volatile float*)g_inc)[ci] = inc;
        __threadfence();
        ((volatile int*)g_flag)[ci] = 2;
    }

    float h = carry;
#pragma unroll 4
    for (int t = 0; t < SC_CHUNK; t++) {
        h = fmaf(smg[t * 128 + thr], h, smv[t * 128 + thr]);
        g_o[base + (size_t)t * HH] = h;
    }
}

// ---------------------------------------------------------------------------
// Gated RMSNorm; caches o in registers; quantizes output row directly.
// ---------------------------------------------------------------------------
__global__ __launch_bounds__(256) void norm_kernel(const float* __restrict__ w)
{
    const int m = blockIdx.x;
    const size_t row = (size_t)m * HH;
    const int t = threadIdx.x;
    float xs[8];
    float s = 0.0f;
#pragma unroll
    for (int it = 0; it < 2; it++) {
        int d4 = (it * 256 + t) * 4;
        float4 x = *(const float4*)&g_o[row + d4];
        xs[it*4+0] = x.x; xs[it*4+1] = x.y; xs[it*4+2] = x.z; xs[it*4+3] = x.w;
        s = fmaf(x.x, x.x, fmaf(x.y, x.y, fmaf(x.z, x.z, fmaf(x.w, x.w, s))));
    }
    __shared__ float red[8];
#pragma unroll
    for (int o = 16; o; o >>= 1) s += __shfl_xor_sync(0xffffffffu, s, o);
    if ((t & 31) == 0) red[t >> 5] = s;
    __syncthreads();
    if (t < 8) {
        float tt = red[t];
#pragma unroll
        for (int o = 4; o; o >>= 1) tt += __shfl_xor_sync(0xffu, tt, o);
        if (t == 0) red[0] = tt;
    }
    __syncthreads();
    const float rms = rsqrtf(red[0] / (float)HH + 1e-5f);

    float y[8];
    float mx = 0.f;
#pragma unroll
    for (int it = 0; it < 2; it++) {
        int d4 = (it * 256 + t) * 4;
        float4 gp = *(const float4*)&g_gp[row + d4];
        float4 wv = *(const float4*)&w[d4];
        y[it*4+0] = xs[it*4+0] * rms * wv.x * gp.x * sigf(gp.x);
        y[it*4+1] = xs[it*4+1] * rms * wv.y * gp.y * sigf(gp.y);
        y[it*4+2] = xs[it*4+2] * rms * wv.z * gp.z * sigf(gp.z);
        y[it*4+3] = xs[it*4+3] * rms * wv.w * gp.w * sigf(gp.w);
#pragma unroll
        for (int j = 0; j < 4; j++) mx = fmaxf(mx, fabsf(y[it*4+j]));
    }
    __syncthreads();
#pragma unroll
    for (int o = 16; o; o >>= 1) mx = fmaxf(mx, __shfl_xor_sync(0xffffffffu, mx, o));
    if ((t & 31) == 0) red[t >> 5] = mx;
    __syncthreads();
    if (t < 8) {
        float mm = red[t];
#pragma unroll
        for (int o = 4; o; o >>= 1) mm = fmaxf(mm, __shfl_xor_sync(0xffu, mm, o));
        if (t == 0) red[0] = mm;
    }
    __syncthreads();
    mx = red[0];
    const float sc = (mx > 0.f) ? mx / 127.f : 1.f;
    const float inv = 127.f * rcpa(fmaxf(mx, 1e-30f));
#pragma unroll
    for (int it = 0; it < 2; it++) {
        int d4 = (it * 256 + t) * 4;
        int a0[4], a1[4];
#pragma unroll
        for (int j = 0; j < 4; j++) {
            float q = y[it*4+j] * inv;
            float r0 = rintf(q);
            a0[j] = (int)r0;
            a1[j] = (int)rintf((q - r0) * 128.f);
        }
        *(uint32_t*)&g_X0[row + d4] = pack4(a0[0],a0[1],a0[2],a0[3]);
        *(uint32_t*)&g_X1[row + d4] = pack4(a1[0],a1[1],a1[2],a1[3]);
    }
    if (t == 0) g_sx[m] = sc;
}

// ---------------------------------------------------------------------------
// Launch
// ---------------------------------------------------------------------------
extern "C" void kernel_launch(void* const* d_in, const int* in_sizes, int n_in,
                              void* d_out, int out_size)
{
    const float* X  = (const float*)d_in[0];
    const float* Wi = (const float*)d_in[1];
    const float* Wf = (const float*)d_in[2];
    const float* Wg = (const float*)d_in[3];
    const float* Wo = (const float*)d_in[4];
    const float* gw = (const float*)d_in[5];
    float* out = (float*)d_out;

    cudaFuncSetAttribute(gemm_mma,  cudaFuncAttributeMaxDynamicSharedMemorySize, 2 * STGB);
    cudaFuncSetAttribute(scan_fused, cudaFuncAttributeMaxDynamicSharedMemorySize,
                         2 * SC_CHUNK * 128 * (int)sizeof(float));

    int8_t *x0, *x1;
    float *sx;
    cudaGetSymbolAddress((void**)&x0,  g_X0);
    cudaGetSymbolAddress((void**)&x1,  g_X1);
    cudaGetSymbolAddress((void**)&sx,  g_sx);
    float *pi, *pf, *pg2;
    cudaGetSymbolAddress((void**)&pi,  g_gate);
    cudaGetSymbolAddress((void**)&pf,  g_v);
    cudaGetSymbolAddress((void**)&pg2, g_gp);

    // quantize X + 4 weights (single launch); also resets lookback flags
    quant_all_kernel<<<dim3(HH, 5), 256>>>(X, Wi, Wf, Wg, Wo);

    // i/f/g projections (raw) via int8 tensor cores — CTA 128x128, KC=128
    gemm_mma<<<dim3(HH/128, MM/128, 3), NTHR, 2*STGB>>>(x0, x1, sx, 0, 0, pi, pf, pg2);

    // fused gating + linear recurrence (single pass, decoupled lookback)
    scan_fused<<<dim3(HH/128, BB, SC_NCH), 128,
                 2 * SC_CHUNK * 128 * sizeof(float)>>>();

    // gated RMSNorm -> quantized o (reuses g_X0/g_X1/g_sx)
    norm_kernel<<<MM, 256>>>(gw);

    // output projection -> d_out (streaming stores)
    gemm_mma<<<dim3(HH/128, MM/128, 1), NTHR, 2*STGB>>>(x0, x1, sx, 3, 1, out, out, out);
}